// round 2
// baseline (speedup 1.0000x reference)
#include <cuda_runtime.h>

#define NROWS 16384
#define NCOLS 1024
#define F4_PER_ROW (NCOLS / 4)        // 256
#define MAIN_BLOCKS 1024
#define MAIN_THREADS 256
#define ROWS_PER_BLOCK (NROWS / MAIN_BLOCKS)   // 16

__device__ float g_colsum[NCOLS];
__device__ float g_sqsum;

__global__ void l2_zero_kernel() {
    int t = threadIdx.x;
    if (t < NCOLS) g_colsum[t] = 0.0f;
    if (t == 0) g_sqsum = 0.0f;
}

__device__ __forceinline__ float warp_reduce_sum(float v) {
    #pragma unroll
    for (int off = 16; off > 0; off >>= 1)
        v += __shfl_xor_sync(0xFFFFFFFFu, v, off);
    return v;
}

__global__ void __launch_bounds__(MAIN_THREADS)
l2_main_kernel(const float* __restrict__ feats) {
    const int t = threadIdx.x;                 // 0..255, owns float4 column-group t
    const float4* __restrict__ f4 = reinterpret_cast<const float4*>(feats);

    float4 cs = make_float4(0.f, 0.f, 0.f, 0.f);
    float sq = 0.f;

    // Each block owns a contiguous stripe of ROWS_PER_BLOCK rows; unroll so
    // ptxas front-batches 8 independent LDG.128s (deep MLP hides DRAM latency).
    const int row0 = blockIdx.x * ROWS_PER_BLOCK;
    #pragma unroll 8
    for (int r = 0; r < ROWS_PER_BLOCK; r++) {
        float4 v = __ldg(&f4[(row0 + r) * F4_PER_ROW + t]);
        cs.x += v.x; cs.y += v.y; cs.z += v.z; cs.w += v.w;
        sq = fmaf(v.x, v.x, sq);
        sq = fmaf(v.y, v.y, sq);
        sq = fmaf(v.z, v.z, sq);
        sq = fmaf(v.w, v.w, sq);
    }

    // Column partial sums: each thread owns distinct addresses -> no intra-block
    // contention; cross-block contention = gridDim per address (REDG, cheap).
    atomicAdd(&g_colsum[4 * t + 0], cs.x);
    atomicAdd(&g_colsum[4 * t + 1], cs.y);
    atomicAdd(&g_colsum[4 * t + 2], cs.z);
    atomicAdd(&g_colsum[4 * t + 3], cs.w);

    // Block-reduce the squared-sum, one atomic per block.
    __shared__ float s_warp[MAIN_THREADS / 32];
    float wsum = warp_reduce_sum(sq);
    int lane = t & 31, wid = t >> 5;
    if (lane == 0) s_warp[wid] = wsum;
    __syncthreads();
    if (wid == 0) {
        float v = (lane < MAIN_THREADS / 32) ? s_warp[lane] : 0.f;
        v = warp_reduce_sum(v);
        if (lane == 0) atomicAdd(&g_sqsum, v);
    }
}

__global__ void __launch_bounds__(NCOLS)
l2_final_kernel(float* __restrict__ out) {
    const int t = threadIdx.x;                 // 0..1023
    float c = g_colsum[t];
    float v = c * c;

    __shared__ float s_warp[NCOLS / 32];
    float wsum = warp_reduce_sum(v);
    int lane = t & 31, wid = t >> 5;
    if (lane == 0) s_warp[wid] = wsum;
    __syncthreads();
    if (wid == 0) {
        float d = (lane < NCOLS / 32) ? s_warp[lane] : 0.f;
        d = warp_reduce_sum(d);
        if (lane == 0) {
            double sqtot = (double)g_sqsum;
            double dot = (double)d;
            double pair_sum = (double)NROWS * sqtot - dot;
            double count = (double)NROWS * (NROWS - 1) / 2.0;
            out[0] = (float)exp(-pair_sum / count);
        }
    }
}

extern "C" void kernel_launch(void* const* d_in, const int* in_sizes, int n_in,
                              void* d_out, int out_size) {
    const float* feats = (const float*)d_in[0];
    float* out = (float*)d_out;

    l2_zero_kernel<<<1, NCOLS>>>();
    l2_main_kernel<<<MAIN_BLOCKS, MAIN_THREADS>>>(feats);
    l2_final_kernel<<<1, NCOLS>>>(out);
}

// round 3
// speedup vs baseline: 1.7947x; 1.7947x over previous
#include <cuda_runtime.h>
#include <math.h>

#define NROWS 16384
#define NCOLS 1024
#define F4_PER_ROW (NCOLS / 4)        // 256
#define BLOCKS 592                    // 4 CTAs per SM on 148 SMs: perfect balance
#define THREADS 256

__device__ float g_colsum[NCOLS];     // zero-initialized at module load
__device__ float g_sqsum;
__device__ unsigned int g_count;

__device__ __forceinline__ float warp_reduce_sum(float v) {
    #pragma unroll
    for (int off = 16; off > 0; off >>= 1)
        v += __shfl_xor_sync(0xFFFFFFFFu, v, off);
    return v;
}

__global__ void __launch_bounds__(THREADS)
l2_fused_kernel(const float* __restrict__ feats, float* __restrict__ out) {
    const int t = threadIdx.x;                 // owns float4 column-group t
    const int bid = blockIdx.x;
    const float4* __restrict__ f4 = reinterpret_cast<const float4*>(feats);

    // Balanced contiguous row stripes: rpb=27, first 400 blocks get 28.
    const int rpb  = NROWS / BLOCKS;           // 27
    const int rem  = NROWS % BLOCKS;           // 400
    const int row0 = bid * rpb + (bid < rem ? bid : rem);
    const int nrows = rpb + (bid < rem ? 1 : 0);

    // Two accumulator sets to split dependency chains.
    float4 cs0 = make_float4(0.f, 0.f, 0.f, 0.f);
    float4 cs1 = make_float4(0.f, 0.f, 0.f, 0.f);
    float sq0 = 0.f, sq1 = 0.f;

    const float4* p = f4 + (size_t)row0 * F4_PER_ROW + t;
    int r = 0;
    #pragma unroll 4
    for (; r + 1 < nrows; r += 2) {
        float4 a = __ldg(p);                   p += F4_PER_ROW;
        float4 b = __ldg(p);                   p += F4_PER_ROW;
        cs0.x += a.x; cs0.y += a.y; cs0.z += a.z; cs0.w += a.w;
        sq0 = fmaf(a.x, a.x, sq0); sq0 = fmaf(a.y, a.y, sq0);
        sq0 = fmaf(a.z, a.z, sq0); sq0 = fmaf(a.w, a.w, sq0);
        cs1.x += b.x; cs1.y += b.y; cs1.z += b.z; cs1.w += b.w;
        sq1 = fmaf(b.x, b.x, sq1); sq1 = fmaf(b.y, b.y, sq1);
        sq1 = fmaf(b.z, b.z, sq1); sq1 = fmaf(b.w, b.w, sq1);
    }
    if (r < nrows) {
        float4 a = __ldg(p);
        cs0.x += a.x; cs0.y += a.y; cs0.z += a.z; cs0.w += a.w;
        sq0 = fmaf(a.x, a.x, sq0); sq0 = fmaf(a.y, a.y, sq0);
        sq0 = fmaf(a.z, a.z, sq0); sq0 = fmaf(a.w, a.w, sq0);
    }
    cs0.x += cs1.x; cs0.y += cs1.y; cs0.z += cs1.z; cs0.w += cs1.w;
    float sq = sq0 + sq1;

    // Per-thread distinct addresses; cross-block contention = 592 per address.
    atomicAdd(&g_colsum[4 * t + 0], cs0.x);
    atomicAdd(&g_colsum[4 * t + 1], cs0.y);
    atomicAdd(&g_colsum[4 * t + 2], cs0.z);
    atomicAdd(&g_colsum[4 * t + 3], cs0.w);

    // Block-reduce sq, one atomic per block.
    __shared__ float s_warp[THREADS / 32];
    __shared__ int s_last;
    float wsum = warp_reduce_sum(sq);
    int lane = t & 31, wid = t >> 5;
    if (lane == 0) s_warp[wid] = wsum;
    __syncthreads();
    if (wid == 0) {
        float v = (lane < THREADS / 32) ? s_warp[lane] : 0.f;
        v = warp_reduce_sum(v);
        if (lane == 0) atomicAdd(&g_sqsum, v);
    }

    // Last-block finalize: fence so our atomics are globally visible, then vote.
    __threadfence();
    if (t == 0) {
        unsigned int prev = atomicAdd(&g_count, 1u);
        s_last = (prev == BLOCKS - 1u) ? 1 : 0;
    }
    __syncthreads();

    if (s_last) {
        // All 592 blocks' atomics are visible (each fenced before incrementing).
        // Use L1-bypassing loads to read the L2-resident accumulators.
        float d = 0.f;
        #pragma unroll
        for (int i = t; i < NCOLS; i += THREADS) {
            float c = __ldcg(&g_colsum[i]);
            d = fmaf(c, c, d);
            g_colsum[i] = 0.f;                 // reset for next graph replay
        }
        float wd = warp_reduce_sum(d);
        if (lane == 0) s_warp[wid] = wd;
        __syncthreads();
        if (wid == 0) {
            float v = (lane < THREADS / 32) ? s_warp[lane] : 0.f;
            v = warp_reduce_sum(v);
            if (lane == 0) {
                double sqtot = (double)__ldcg(&g_sqsum);
                double dot = (double)v;
                double pair_sum = (double)NROWS * sqtot - dot;
                double count = (double)NROWS * (NROWS - 1) / 2.0;
                out[0] = (float)exp(-pair_sum / count);
                g_sqsum = 0.f;                 // reset state for next replay
                g_count = 0u;
            }
        }
    }
}

extern "C" void kernel_launch(void* const* d_in, const int* in_sizes, int n_in,
                              void* d_out, int out_size) {
    const float* feats = (const float*)d_in[0];
    float* out = (float*)d_out;
    l2_fused_kernel<<<BLOCKS, THREADS>>>(feats, out);
}

// round 4
// speedup vs baseline: 2.8470x; 1.5864x over previous
#include <cuda_runtime.h>
#include <math.h>

#define NROWS 16384
#define NCOLS 1024
#define F4_PER_ROW (NCOLS / 4)        // 256
#define BLOCKS 1184                   // 8 CTAs/SM on 148 SMs: one full wave, occ 100%
#define THREADS 256
#define NBUCKETS 8                    // spread column atomics 8-way

__device__ float g_colsum[NBUCKETS][NCOLS];   // zero-init at module load
__device__ float g_sqsum;
__device__ unsigned int g_count;

__device__ __forceinline__ float warp_reduce_sum(float v) {
    #pragma unroll
    for (int off = 16; off > 0; off >>= 1)
        v += __shfl_xor_sync(0xFFFFFFFFu, v, off);
    return v;
}

__global__ void __launch_bounds__(THREADS, 8)
l2_fused_kernel(const float* __restrict__ feats, float* __restrict__ out) {
    const int t = threadIdx.x;                 // owns float4 column-group t
    const int bid = blockIdx.x;
    const float4* __restrict__ f4 = reinterpret_cast<const float4*>(feats);

    // Balanced contiguous row stripes: rpb=13, first 992 blocks get 14.
    const int rpb  = NROWS / BLOCKS;           // 13
    const int rem  = NROWS % BLOCKS;           // 992
    const int row0 = bid * rpb + (bid < rem ? bid : rem);
    const int nrows = rpb + (bid < rem ? 1 : 0);

    float4 cs0 = make_float4(0.f, 0.f, 0.f, 0.f);
    float4 cs1 = make_float4(0.f, 0.f, 0.f, 0.f);
    float sq0 = 0.f, sq1 = 0.f;

    const float4* p = f4 + (size_t)row0 * F4_PER_ROW + t;
    int r = 0;
    for (; r + 1 < nrows; r += 2) {
        float4 a = __ldg(p);                   p += F4_PER_ROW;
        float4 b = __ldg(p);                   p += F4_PER_ROW;
        cs0.x += a.x; cs0.y += a.y; cs0.z += a.z; cs0.w += a.w;
        sq0 = fmaf(a.x, a.x, sq0); sq0 = fmaf(a.y, a.y, sq0);
        sq0 = fmaf(a.z, a.z, sq0); sq0 = fmaf(a.w, a.w, sq0);
        cs1.x += b.x; cs1.y += b.y; cs1.z += b.z; cs1.w += b.w;
        sq1 = fmaf(b.x, b.x, sq1); sq1 = fmaf(b.y, b.y, sq1);
        sq1 = fmaf(b.z, b.z, sq1); sq1 = fmaf(b.w, b.w, sq1);
    }
    if (r < nrows) {
        float4 a = __ldg(p);
        cs0.x += a.x; cs0.y += a.y; cs0.z += a.z; cs0.w += a.w;
        sq0 = fmaf(a.x, a.x, sq0); sq0 = fmaf(a.y, a.y, sq0);
        sq0 = fmaf(a.z, a.z, sq0); sq0 = fmaf(a.w, a.w, sq0);
    }
    cs0.x += cs1.x; cs0.y += cs1.y; cs0.z += cs1.z; cs0.w += cs1.w;
    float sq = sq0 + sq1;

    // Bucketed column atomics: 8x the addresses/lines -> 8x less per-slice
    // serialization at the L2 atomic ALUs. Contention = 148 blocks per address.
    float* bucket = g_colsum[bid & (NBUCKETS - 1)];
    atomicAdd(&bucket[4 * t + 0], cs0.x);
    atomicAdd(&bucket[4 * t + 1], cs0.y);
    atomicAdd(&bucket[4 * t + 2], cs0.z);
    atomicAdd(&bucket[4 * t + 3], cs0.w);

    // Block-reduce sq, one atomic per block.
    __shared__ float s_warp[THREADS / 32];
    __shared__ int s_last;
    float wsum = warp_reduce_sum(sq);
    int lane = t & 31, wid = t >> 5;
    if (lane == 0) s_warp[wid] = wsum;
    __syncthreads();
    if (wid == 0) {
        float v = (lane < THREADS / 32) ? s_warp[lane] : 0.f;
        v = warp_reduce_sum(v);
        if (lane == 0) atomicAdd(&g_sqsum, v);
    }

    // Last-block finalize: fence so our atomics are globally visible, then vote.
    __threadfence();
    if (t == 0) {
        unsigned int prev = atomicAdd(&g_count, 1u);
        s_last = (prev == BLOCKS - 1u) ? 1 : 0;
    }
    __syncthreads();

    if (s_last) {
        // Fold the 8 buckets, square, and reset state for the next graph replay.
        float d = 0.f;
        #pragma unroll
        for (int i = t; i < NCOLS; i += THREADS) {
            float c = 0.f;
            #pragma unroll
            for (int b = 0; b < NBUCKETS; b++) {
                c += __ldcg(&g_colsum[b][i]);
                g_colsum[b][i] = 0.f;
            }
            d = fmaf(c, c, d);
        }
        float wd = warp_reduce_sum(d);
        if (lane == 0) s_warp[wid] = wd;
        __syncthreads();
        if (wid == 0) {
            float v = (lane < THREADS / 32) ? s_warp[lane] : 0.f;
            v = warp_reduce_sum(v);
            if (lane == 0) {
                double sqtot = (double)__ldcg(&g_sqsum);
                double dot = (double)v;
                double pair_sum = (double)NROWS * sqtot - dot;
                double count = (double)NROWS * (NROWS - 1) / 2.0;
                out[0] = (float)exp(-pair_sum / count);
                g_sqsum = 0.f;
                g_count = 0u;
            }
        }
    }
}

extern "C" void kernel_launch(void* const* d_in, const int* in_sizes, int n_in,
                              void* d_out, int out_size) {
    const float* feats = (const float*)d_in[0];
    float* out = (float*)d_out;
    l2_fused_kernel<<<BLOCKS, THREADS>>>(feats, out);
}

// round 8
// speedup vs baseline: 4.0583x; 1.4255x over previous
#include <cuda_runtime.h>
#include <math.h>

#define NROWS 16384
#define NCOLS 1024
#define F4_PER_ROW (NCOLS / 4)        // 256
#define BLOCKS 296                    // 2 CTAs/SM x 148 SMs, 64 warps/SM
#define THREADS 1024
#define NBUCKETS 8

__device__ float g_colsum[NBUCKETS][NCOLS];   // zero-init at module load
__device__ float g_sqsum;
__device__ unsigned int g_count;

__device__ __forceinline__ float warp_reduce_sum(float v) {
    #pragma unroll
    for (int off = 16; off > 0; off >>= 1)
        v += __shfl_xor_sync(0xFFFFFFFFu, v, off);
    return v;
}

__global__ void __launch_bounds__(THREADS, 2)
l2_fused_kernel(const float* __restrict__ feats, float* __restrict__ out) {
    const int t = threadIdx.x;
    const int bid = blockIdx.x;
    const int sub = t >> 8;            // 0..3: which of 4 concurrent rows
    const int cg  = t & 255;           // float4 column group
    const float4* __restrict__ f4 = reinterpret_cast<const float4*>(feats);

    // Balanced contiguous stripes: rpb=55, first 104 blocks get 56.
    const int rpb  = NROWS / BLOCKS;           // 55
    const int rem  = NROWS % BLOCKS;           // 104
    const int row0 = bid * rpb + (bid < rem ? bid : rem);
    const int nrows = rpb + (bid < rem ? 1 : 0);

    float4 cs = make_float4(0.f, 0.f, 0.f, 0.f);
    float sq = 0.f;

    // Thread handles rows row0+sub, row0+sub+4, ... ; unroll 4 => 4 independent
    // LDG.128 in flight per thread (MLP 4), 64 warps/SM on top.
    const float4* p = f4 + (size_t)(row0 + sub) * F4_PER_ROW + cg;
    #pragma unroll 4
    for (int r = sub; r < nrows; r += 4) {
        float4 v = __ldg(p);
        p += 4 * F4_PER_ROW;
        cs.x += v.x; cs.y += v.y; cs.z += v.z; cs.w += v.w;
        sq = fmaf(v.x, v.x, sq); sq = fmaf(v.y, v.y, sq);
        sq = fmaf(v.z, v.z, sq); sq = fmaf(v.w, v.w, sq);
    }

    // Combine the 4 subrow partials per column group in SMEM, then only
    // subrow 0 (warps 0-7) issues global atomics: 1024 per block (4x fewer
    // than before => ~4x less LTS atomic-ALU traffic chip-wide).
    __shared__ float4 s_part[3][256];          // 12 KB
    __shared__ float s_warp[THREADS / 32];
    __shared__ int s_last;

    if (sub != 0) s_part[sub - 1][cg] = cs;

    // Block-reduce sq while the partials land.
    float wsum = warp_reduce_sum(sq);
    int lane = t & 31, wid = t >> 5;
    if (lane == 0) s_warp[wid] = wsum;
    __syncthreads();

    if (sub == 0) {
        float4 a = s_part[0][cg], b = s_part[1][cg], c = s_part[2][cg];
        cs.x += a.x + b.x + c.x;
        cs.y += a.y + b.y + c.y;
        cs.z += a.z + b.z + c.z;
        cs.w += a.w + b.w + c.w;
        float* bucket = g_colsum[bid & (NBUCKETS - 1)];
        atomicAdd(&bucket[4 * cg + 0], cs.x);
        atomicAdd(&bucket[4 * cg + 1], cs.y);
        atomicAdd(&bucket[4 * cg + 2], cs.z);
        atomicAdd(&bucket[4 * cg + 3], cs.w);
    }
    if (wid == 0) {
        float v = (lane < THREADS / 32) ? s_warp[lane] : 0.f;
        v = warp_reduce_sum(v);
        if (lane == 0) atomicAdd(&g_sqsum, v);
    }

    // Last-block vote (fence makes our atomics globally visible first).
    __threadfence();
    if (t == 0) {
        unsigned int prev = atomicAdd(&g_count, 1u);
        s_last = (prev == BLOCKS - 1u) ? 1 : 0;
    }
    __syncthreads();

    if (s_last) {
        // Fold 8 buckets, square, reset state for the next graph replay.
        float c = 0.f;
        #pragma unroll
        for (int b = 0; b < NBUCKETS; b++) {
            c += __ldcg(&g_colsum[b][t]);
            g_colsum[b][t] = 0.f;
        }
        float d = c * c;
        float wd = warp_reduce_sum(d);
        if (lane == 0) s_warp[wid] = wd;
        __syncthreads();
        if (wid == 0) {
            float v = (lane < THREADS / 32) ? s_warp[lane] : 0.f;
            v = warp_reduce_sum(v);
            if (lane == 0) {
                double sqtot = (double)__ldcg(&g_sqsum);
                double dot = (double)v;
                double pair_sum = (double)NROWS * sqtot - dot;
                double count = (double)NROWS * (NROWS - 1) / 2.0;
                out[0] = (float)exp(-pair_sum / count);
                g_sqsum = 0.f;
                g_count = 0u;
            }
        }
    }
}

extern "C" void kernel_launch(void* const* d_in, const int* in_sizes, int n_in,
                              void* d_out, int out_size) {
    const float* feats = (const float*)d_in[0];
    float* out = (float*)d_out;
    l2_fused_kernel<<<BLOCKS, THREADS>>>(feats, out);
}